// round 9
// baseline (speedup 1.0000x reference)
#include <cuda_runtime.h>
#include <cstdint>

#define N_USERS 50000
#define N_ITEMS 100000
#define N_NODES (N_USERS + N_ITEMS)
#define D 64
#define EPS 1e-6f
#define E_MAX 2400000
#define SCAN_BLOCK 1024
#define N_SCAN_BLOCKS ((N_NODES + SCAN_BLOCK - 1) / SCAN_BLOCK)   // 147

// ---------------------------------------------------------------------------
// Static scratch (allocation-free). Device symbols are ONLY referenced from
// device code (host-side use passes the host shadow address via ATS — R2 bug).
// ---------------------------------------------------------------------------
__device__ float g_embs[4][N_NODES * D];       // fp32 embeddings (layers 0..3)
__device__ int   g_cnt[N_NODES];               // per-row edge counts
__device__ int   g_row_ptr[N_NODES + 1];       // CSR row pointers
__device__ int   g_pos[E_MAX];                 // per-edge within-row rank (from hist)
__device__ int   g_csr_edge[E_MAX * 2];        // interleaved {col, val-bits} pairs
__device__ int   g_is64;                       // index dtype flag
// decoupled-lookback scan state (reset every launch by prep_kernel)
__device__ volatile int g_flag[N_SCAN_BLOCKS];
__device__ volatile int g_aggv[N_SCAN_BLOCKS];
__device__ volatile int g_incv[N_SCAN_BLOCKS];

// ---------------------------------------------------------------------------
// Prep: zero g_cnt + scan flags; block 0 detects index dtype (int64 vs int32)
// in parallel.
// ---------------------------------------------------------------------------
__global__ void prep_kernel(const void* rows, int n) {
    int i = blockIdx.x * blockDim.x + threadIdx.x;
    if (i < N_NODES) g_cnt[i] = 0;
    if (i < N_SCAN_BLOCKS) { g_flag[i] = 0; g_aggv[i] = 0; g_incv[i] = 0; }

    if (blockIdx.x == 0) {
        __shared__ int s_bad;
        if (threadIdx.x == 0) s_bad = 0;
        __syncthreads();
        int lim = (n < 64) ? n : 64;
        if ((int)threadIdx.x < lim) {
            long long v = ((const long long*)rows)[threadIdx.x];
            if (v < 0 || v >= (long long)N_NODES) atomicOr(&s_bad, 1);
        }
        __syncthreads();
        if (threadIdx.x == 0) g_is64 = s_bad ? 0 : 1;
    }
}

__device__ __forceinline__ int load_idx(const void* p, int e) {
    if (g_is64) return (int)((const long long*)p)[e];
    return ((const int*)p)[e];
}

// ---------------------------------------------------------------------------
// Histogram + rank stash: the atomic's return value IS the edge's final
// within-row slot, so the scatter pass needs no atomics at all.
// ---------------------------------------------------------------------------
__global__ void hist_kernel(const void* __restrict__ rows, int n_edges) {
    int e = blockIdx.x * blockDim.x + threadIdx.x;
    if (e >= n_edges) return;
    int r = load_idx(rows, e);
    g_pos[e] = atomicAdd(&g_cnt[r], 1);
}

// ---------------------------------------------------------------------------
// Single-launch decoupled-lookback exclusive scan of g_cnt -> g_row_ptr.
// Warp-parallel lookback (32 predecessors per poll window).
// ---------------------------------------------------------------------------
__global__ void scan_kernel() {
    __shared__ int sh[SCAN_BLOCK];
    __shared__ int s_exc;
    int b = blockIdx.x;
    int i = b * SCAN_BLOCK + threadIdx.x;
    int v = (i < N_NODES) ? g_cnt[i] : 0;
    sh[threadIdx.x] = v;
    __syncthreads();
    #pragma unroll
    for (int off = 1; off < SCAN_BLOCK; off <<= 1) {
        int t = (threadIdx.x >= off) ? sh[threadIdx.x - off] : 0;
        __syncthreads();
        sh[threadIdx.x] += t;
        __syncthreads();
    }
    int total = sh[SCAN_BLOCK - 1];

    if (threadIdx.x < 32) {                 // lookback warp
        int lane = threadIdx.x;
        if (b == 0) {
            if (lane == 0) {
                g_incv[0] = total;
                __threadfence();
                g_flag[0] = 2;
                s_exc = 0;
            }
        } else {
            if (lane == 0) {
                g_aggv[b] = total;
                __threadfence();
                g_flag[b] = 1;
            }
            int run = 0;
            int base = b;                    // window is [base-32, base)
            while (true) {
                int p = base - 32 + lane;
                int f, val;
                if (p >= 0) {
                    while ((f = g_flag[p]) == 0) { }
                    __threadfence();
                    val = (f == 2) ? g_incv[p] : g_aggv[p];
                } else {
                    f = 2; val = 0;          // virtual inclusive prefix of 0
                }
                unsigned mask = __ballot_sync(0xFFFFFFFFu, f == 2);
                if (mask) {
                    int hi = 31 - __clz(mask);
                    int contrib = (lane >= hi) ? val : 0;
                    #pragma unroll
                    for (int o = 16; o; o >>= 1)
                        contrib += __shfl_xor_sync(0xFFFFFFFFu, contrib, o);
                    run += contrib;
                    break;
                } else {
                    int contrib = val;
                    #pragma unroll
                    for (int o = 16; o; o >>= 1)
                        contrib += __shfl_xor_sync(0xFFFFFFFFu, contrib, o);
                    run += contrib;
                    base -= 32;
                }
            }
            if (lane == 0) {
                g_incv[b] = run + total;
                __threadfence();
                g_flag[b] = 2;
                s_exc = run;
            }
        }
    }
    __syncthreads();

    if (i < N_NODES) {
        int inc = sh[threadIdx.x] + s_exc;
        g_row_ptr[i] = inc - v;              // exclusive
        if (i == N_NODES - 1) g_row_ptr[N_NODES] = inc;
    }
}

// ---------------------------------------------------------------------------
// Scatter — atomic-free, ONE packed 8B store per edge (one scattered L2
// sector instead of two; the two-4B-store version measured 38.6us at 68.6%
// L2 with issue 7%, i.e. sector-bound).
// ---------------------------------------------------------------------------
__global__ void scatter_kernel(const void* __restrict__ rows,
                               const void* __restrict__ cols,
                               const float* __restrict__ vals,
                               int n_edges) {
    int e = blockIdx.x * blockDim.x + threadIdx.x;
    if (e >= n_edges) return;
    int r = load_idx(rows, e);
    int c = load_idx(cols, e);
    float v = vals[e];
    int slot = __ldg(&g_row_ptr[r]) + g_pos[e];
    ((int2*)g_csr_edge)[slot] = make_int2(c, __float_as_int(v));
}

// ---------------------------------------------------------------------------
// Init: g_embs[0] = concat(user_emb, item_emb)
// ---------------------------------------------------------------------------
__global__ void init_kernel(const float* __restrict__ user_emb,
                            const float* __restrict__ item_emb) {
    int i = blockIdx.x * blockDim.x + threadIdx.x;   // float4 index
    const int total4 = N_NODES * D / 4;
    if (i >= total4) return;
    const int usplit = N_USERS * D / 4;
    float4 v = (i < usplit) ? ((const float4*)user_emb)[i]
                            : ((const float4*)item_emb)[i - usplit];
    ((float4*)g_embs[0])[i] = v;
}

// ---------------------------------------------------------------------------
// Fused layer (R5-proven loop shape): per-node CSR gather-sum + growth
// gating. One warp per node; lane owns a float2 slice; 2-way unroll; fp32.
// Edge stream is interleaved {col,val} but read with SCALAR 4B loads (the
// LDG.64 form regressed in R4/R7); streamed with .cs to not pollute L2.
// ---------------------------------------------------------------------------
__global__ void layer_kernel(int l) {
    int node = blockIdx.x * (blockDim.x >> 5) + (threadIdx.x >> 5);
    int lane = threadIdx.x & 31;
    if (node >= N_NODES) return;

    const float2* base = (const float2*)g_embs[l];
    float2*       outp = (float2*)g_embs[l + 1];

    int beg = __ldg(&g_row_ptr[node]);
    int end = __ldg(&g_row_ptr[node + 1]);

    float2 acc = make_float2(0.f, 0.f);

    int i = beg;
    for (; i + 1 < end; i += 2) {
        int   c0 = __ldcs(&g_csr_edge[2 * i]);
        float v0 = __int_as_float(__ldcs(&g_csr_edge[2 * i + 1]));
        int   c1 = __ldcs(&g_csr_edge[2 * i + 2]);
        float v1 = __int_as_float(__ldcs(&g_csr_edge[2 * i + 3]));
        float2 x0 = base[c0 * 32 + lane];
        float2 x1 = base[c1 * 32 + lane];
        acc.x += v0 * x0.x + v1 * x1.x;
        acc.y += v0 * x0.y + v1 * x1.y;
    }
    if (i < end) {
        int   c = __ldcs(&g_csr_edge[2 * i]);
        float v = __int_as_float(__ldcs(&g_csr_edge[2 * i + 1]));
        float2 x = base[c * 32 + lane];
        acc.x += v * x.x;
        acc.y += v * x.y;
    }

    float2 o = base[node * 32 + lane];

    float dx = o.x - acc.x + EPS;
    float dy = o.y - acc.y + EPS;
    float s = dx * dx + dy * dy;
    #pragma unroll
    for (int off = 16; off; off >>= 1)
        s += __shfl_xor_sync(0xFFFFFFFFu, s, off);

    float osn   = sqrtf(s);
    float dnew  = log1pf(osn);
    float inv   = 1.0f / (1.0f + dnew);
    float w_old = inv;
    float w_new = dnew * inv;

    float2 r;
    r.x = w_old * o.x + w_new * acc.x;
    r.y = w_old * o.y + w_new * acc.y;
    outp[node * 32 + lane] = r;
}

// ---------------------------------------------------------------------------
// Gather: out row = mean over the 4 layer embeddings of the selected node.
// ---------------------------------------------------------------------------
__global__ void gather_kernel(const void* __restrict__ user_id,
                              const void* __restrict__ item_id,
                              float* __restrict__ out,
                              int n_ids) {
    int i = blockIdx.x * (blockDim.x >> 5) + (threadIdx.x >> 5);
    int lane = threadIdx.x & 31;
    if (i >= 2 * n_ids) return;

    int node;
    if (i < n_ids) node = load_idx(user_id, i);
    else           node = N_USERS + load_idx(item_id, i - n_ids);

    int off = node * 32 + lane;
    float2 a0 = ((const float2*)g_embs[0])[off];
    float2 a1 = ((const float2*)g_embs[1])[off];
    float2 a2 = ((const float2*)g_embs[2])[off];
    float2 a3 = ((const float2*)g_embs[3])[off];
    float2 r;
    r.x = (a0.x + a1.x + a2.x + a3.x) * 0.25f;
    r.y = (a0.y + a1.y + a2.y + a3.y) * 0.25f;
    ((float2*)(out + (long long)i * D))[lane] = r;
}

// ---------------------------------------------------------------------------
// kernel_launch
// ---------------------------------------------------------------------------
extern "C" void kernel_launch(void* const* d_in, const int* in_sizes, int n_in,
                              void* d_out, int out_size) {
    const float* user_emb = (const float*)d_in[0];
    const float* item_emb = (const float*)d_in[1];
    const float* adj_vals = (const float*)d_in[2];
    const void*  adj_rows = d_in[3];
    const void*  adj_cols = d_in[4];
    const void*  user_id  = d_in[5];
    const void*  item_id  = d_in[6];
    float* out = (float*)d_out;

    int n_edges = in_sizes[3];
    if (n_edges > E_MAX) n_edges = E_MAX;
    int n_ids = in_sizes[5];

    // 0: prep (zero cnt + scan flags + dtype detect)
    prep_kernel<<<(N_NODES + 255) / 256, 256>>>(adj_rows, n_edges);
    // 1: histogram + per-edge rank stash
    hist_kernel<<<(n_edges + 255) / 256, 256>>>(adj_rows, n_edges);
    // 2: single-launch warp-parallel lookback scan -> row_ptr
    scan_kernel<<<N_SCAN_BLOCKS, SCAN_BLOCK>>>();
    // 3: atomic-free scatter, packed 8B store (profiled slot)
    scatter_kernel<<<(n_edges + 255) / 256, 256>>>(adj_rows, adj_cols, adj_vals, n_edges);
    // 4: emb0 init
    {
        int total4 = N_NODES * D / 4;
        init_kernel<<<(total4 + 255) / 256, 256>>>(user_emb, item_emb);
    }
    // 5-7: fused layers (warp per node, 8 nodes per 256-thread block)
    int layer_blocks = (N_NODES + 7) / 8;
    layer_kernel<<<layer_blocks, 256>>>(0);
    layer_kernel<<<layer_blocks, 256>>>(1);
    layer_kernel<<<layer_blocks, 256>>>(2);
    // 8: final gather + mean
    int gather_rows = 2 * n_ids;
    gather_kernel<<<(gather_rows + 7) / 8, 256>>>(user_id, item_id, out, n_ids);
}

// round 10
// speedup vs baseline: 1.0563x; 1.0563x over previous
#include <cuda_runtime.h>
#include <cstdint>

#define N_USERS 50000
#define N_ITEMS 100000
#define N_NODES (N_USERS + N_ITEMS)
#define D 64
#define EPS 1e-6f
#define E_MAX 2400000
#define SCAN_BLOCK 1024
#define N_SCAN_BLOCKS ((N_NODES + SCAN_BLOCK - 1) / SCAN_BLOCK)   // 147

// ---------------------------------------------------------------------------
// Static scratch (allocation-free). Device symbols are ONLY referenced from
// device code (host-side use passes the host shadow address via ATS — R2 bug).
// ---------------------------------------------------------------------------
__device__ float g_embs[4][N_NODES * D];       // fp32 embeddings (layers 0..3)
__device__ int   g_cnt[N_NODES];               // per-row edge counts
__device__ int   g_row_ptr[N_NODES + 1];       // CSR row pointers
__device__ int   g_pos[E_MAX];                 // per-edge within-row rank (from hist)
__device__ int   g_csr_edge[E_MAX * 2];        // interleaved {col, val-bits} pairs
__device__ int   g_is64;                       // index dtype flag
// decoupled-lookback scan state (reset every launch by prep_kernel)
__device__ volatile int g_flag[N_SCAN_BLOCKS];
__device__ volatile int g_aggv[N_SCAN_BLOCKS];
__device__ volatile int g_incv[N_SCAN_BLOCKS];

// ---------------------------------------------------------------------------
// Prep: zero g_cnt + scan flags; block 0 detects index dtype (int64 vs int32)
// in parallel.
// ---------------------------------------------------------------------------
__global__ void prep_kernel(const void* rows, int n) {
    int i = blockIdx.x * blockDim.x + threadIdx.x;
    if (i < N_NODES) g_cnt[i] = 0;
    if (i < N_SCAN_BLOCKS) { g_flag[i] = 0; g_aggv[i] = 0; g_incv[i] = 0; }

    if (blockIdx.x == 0) {
        __shared__ int s_bad;
        if (threadIdx.x == 0) s_bad = 0;
        __syncthreads();
        int lim = (n < 64) ? n : 64;
        if ((int)threadIdx.x < lim) {
            long long v = ((const long long*)rows)[threadIdx.x];
            if (v < 0 || v >= (long long)N_NODES) atomicOr(&s_bad, 1);
        }
        __syncthreads();
        if (threadIdx.x == 0) g_is64 = s_bad ? 0 : 1;
    }
}

__device__ __forceinline__ int load_idx(const void* p, int e) {
    if (g_is64) return (int)((const long long*)p)[e];
    return ((const int*)p)[e];
}

// ---------------------------------------------------------------------------
// Histogram + rank stash: the atomic's return value IS the edge's final
// within-row slot, so the scatter pass needs no atomics at all.
// ---------------------------------------------------------------------------
__global__ void hist_kernel(const void* __restrict__ rows, int n_edges) {
    int e = blockIdx.x * blockDim.x + threadIdx.x;
    if (e >= n_edges) return;
    int r = load_idx(rows, e);
    g_pos[e] = atomicAdd(&g_cnt[r], 1);
}

// ---------------------------------------------------------------------------
// Single-launch decoupled-lookback exclusive scan of g_cnt -> g_row_ptr.
// Warp-parallel lookback (32 predecessors per poll window).
// ---------------------------------------------------------------------------
__global__ void scan_kernel() {
    __shared__ int sh[SCAN_BLOCK];
    __shared__ int s_exc;
    int b = blockIdx.x;
    int i = b * SCAN_BLOCK + threadIdx.x;
    int v = (i < N_NODES) ? g_cnt[i] : 0;
    sh[threadIdx.x] = v;
    __syncthreads();
    #pragma unroll
    for (int off = 1; off < SCAN_BLOCK; off <<= 1) {
        int t = (threadIdx.x >= off) ? sh[threadIdx.x - off] : 0;
        __syncthreads();
        sh[threadIdx.x] += t;
        __syncthreads();
    }
    int total = sh[SCAN_BLOCK - 1];

    if (threadIdx.x < 32) {                 // lookback warp
        int lane = threadIdx.x;
        if (b == 0) {
            if (lane == 0) {
                g_incv[0] = total;
                __threadfence();
                g_flag[0] = 2;
                s_exc = 0;
            }
        } else {
            if (lane == 0) {
                g_aggv[b] = total;
                __threadfence();
                g_flag[b] = 1;
            }
            int run = 0;
            int base = b;                    // window is [base-32, base)
            while (true) {
                int p = base - 32 + lane;
                int f, val;
                if (p >= 0) {
                    while ((f = g_flag[p]) == 0) { }
                    __threadfence();
                    val = (f == 2) ? g_incv[p] : g_aggv[p];
                } else {
                    f = 2; val = 0;          // virtual inclusive prefix of 0
                }
                unsigned mask = __ballot_sync(0xFFFFFFFFu, f == 2);
                if (mask) {
                    int hi = 31 - __clz(mask);
                    int contrib = (lane >= hi) ? val : 0;
                    #pragma unroll
                    for (int o = 16; o; o >>= 1)
                        contrib += __shfl_xor_sync(0xFFFFFFFFu, contrib, o);
                    run += contrib;
                    break;
                } else {
                    int contrib = val;
                    #pragma unroll
                    for (int o = 16; o; o >>= 1)
                        contrib += __shfl_xor_sync(0xFFFFFFFFu, contrib, o);
                    run += contrib;
                    base -= 32;
                }
            }
            if (lane == 0) {
                g_incv[b] = run + total;
                __threadfence();
                g_flag[b] = 2;
                s_exc = run;
            }
        }
    }
    __syncthreads();

    if (i < N_NODES) {
        int inc = sh[threadIdx.x] + s_exc;
        g_row_ptr[i] = inc - v;              // exclusive
        if (i == N_NODES - 1) g_row_ptr[N_NODES] = inc;
    }
}

// ---------------------------------------------------------------------------
// Scatter — atomic-free, ONE packed 8B store per edge (measured win:
// 38.6us -> 28.2us vs two 4B stores).
// ---------------------------------------------------------------------------
__global__ void scatter_kernel(const void* __restrict__ rows,
                               const void* __restrict__ cols,
                               const float* __restrict__ vals,
                               int n_edges) {
    int e = blockIdx.x * blockDim.x + threadIdx.x;
    if (e >= n_edges) return;
    int r = load_idx(rows, e);
    int c = load_idx(cols, e);
    float v = vals[e];
    int slot = __ldg(&g_row_ptr[r]) + g_pos[e];
    ((int2*)g_csr_edge)[slot] = make_int2(c, __float_as_int(v));
}

// ---------------------------------------------------------------------------
// Init: g_embs[0] = concat(user_emb, item_emb)
// ---------------------------------------------------------------------------
__global__ void init_kernel(const float* __restrict__ user_emb,
                            const float* __restrict__ item_emb) {
    int i = blockIdx.x * blockDim.x + threadIdx.x;   // float4 index
    const int total4 = N_NODES * D / 4;
    if (i >= total4) return;
    const int usplit = N_USERS * D / 4;
    float4 v = (i < usplit) ? ((const float4*)user_emb)[i]
                            : ((const float4*)item_emb)[i - usplit];
    ((float4*)g_embs[0])[i] = v;
}

// ---------------------------------------------------------------------------
// Fused layer (R5-proven loop shape): per-node CSR gather-sum + growth
// gating. One warp per node; lane owns a float2 slice; 2-way unroll; fp32.
// Edge stream: interleaved {col,val}, SCALAR __ldg 4B loads (default cache
// policy — R9's __ldcs evict-first defeated cross-warp sector reuse, +15us).
// ---------------------------------------------------------------------------
__global__ void layer_kernel(int l) {
    int node = blockIdx.x * (blockDim.x >> 5) + (threadIdx.x >> 5);
    int lane = threadIdx.x & 31;
    if (node >= N_NODES) return;

    const float2* base = (const float2*)g_embs[l];
    float2*       outp = (float2*)g_embs[l + 1];

    int beg = __ldg(&g_row_ptr[node]);
    int end = __ldg(&g_row_ptr[node + 1]);

    float2 acc = make_float2(0.f, 0.f);

    int i = beg;
    for (; i + 1 < end; i += 2) {
        int   c0 = __ldg(&g_csr_edge[2 * i]);
        float v0 = __int_as_float(__ldg(&g_csr_edge[2 * i + 1]));
        int   c1 = __ldg(&g_csr_edge[2 * i + 2]);
        float v1 = __int_as_float(__ldg(&g_csr_edge[2 * i + 3]));
        float2 x0 = base[c0 * 32 + lane];
        float2 x1 = base[c1 * 32 + lane];
        acc.x += v0 * x0.x + v1 * x1.x;
        acc.y += v0 * x0.y + v1 * x1.y;
    }
    if (i < end) {
        int   c = __ldg(&g_csr_edge[2 * i]);
        float v = __int_as_float(__ldg(&g_csr_edge[2 * i + 1]));
        float2 x = base[c * 32 + lane];
        acc.x += v * x.x;
        acc.y += v * x.y;
    }

    float2 o = base[node * 32 + lane];

    float dx = o.x - acc.x + EPS;
    float dy = o.y - acc.y + EPS;
    float s = dx * dx + dy * dy;
    #pragma unroll
    for (int off = 16; off; off >>= 1)
        s += __shfl_xor_sync(0xFFFFFFFFu, s, off);

    float osn   = sqrtf(s);
    float dnew  = log1pf(osn);
    float inv   = 1.0f / (1.0f + dnew);
    float w_old = inv;
    float w_new = dnew * inv;

    float2 r;
    r.x = w_old * o.x + w_new * acc.x;
    r.y = w_old * o.y + w_new * acc.y;
    outp[node * 32 + lane] = r;
}

// ---------------------------------------------------------------------------
// Gather: out row = mean over the 4 layer embeddings of the selected node.
// ---------------------------------------------------------------------------
__global__ void gather_kernel(const void* __restrict__ user_id,
                              const void* __restrict__ item_id,
                              float* __restrict__ out,
                              int n_ids) {
    int i = blockIdx.x * (blockDim.x >> 5) + (threadIdx.x >> 5);
    int lane = threadIdx.x & 31;
    if (i >= 2 * n_ids) return;

    int node;
    if (i < n_ids) node = load_idx(user_id, i);
    else           node = N_USERS + load_idx(item_id, i - n_ids);

    int off = node * 32 + lane;
    float2 a0 = ((const float2*)g_embs[0])[off];
    float2 a1 = ((const float2*)g_embs[1])[off];
    float2 a2 = ((const float2*)g_embs[2])[off];
    float2 a3 = ((const float2*)g_embs[3])[off];
    float2 r;
    r.x = (a0.x + a1.x + a2.x + a3.x) * 0.25f;
    r.y = (a0.y + a1.y + a2.y + a3.y) * 0.25f;
    ((float2*)(out + (long long)i * D))[lane] = r;
}

// ---------------------------------------------------------------------------
// kernel_launch
// ---------------------------------------------------------------------------
extern "C" void kernel_launch(void* const* d_in, const int* in_sizes, int n_in,
                              void* d_out, int out_size) {
    const float* user_emb = (const float*)d_in[0];
    const float* item_emb = (const float*)d_in[1];
    const float* adj_vals = (const float*)d_in[2];
    const void*  adj_rows = d_in[3];
    const void*  adj_cols = d_in[4];
    const void*  user_id  = d_in[5];
    const void*  item_id  = d_in[6];
    float* out = (float*)d_out;

    int n_edges = in_sizes[3];
    if (n_edges > E_MAX) n_edges = E_MAX;
    int n_ids = in_sizes[5];

    // 0: prep (zero cnt + scan flags + dtype detect)
    prep_kernel<<<(N_NODES + 255) / 256, 256>>>(adj_rows, n_edges);
    // 1: histogram + per-edge rank stash
    hist_kernel<<<(n_edges + 255) / 256, 256>>>(adj_rows, n_edges);
    // 2: single-launch warp-parallel lookback scan -> row_ptr
    scan_kernel<<<N_SCAN_BLOCKS, SCAN_BLOCK>>>();
    // 3: atomic-free scatter, packed 8B store (profiled slot)
    scatter_kernel<<<(n_edges + 255) / 256, 256>>>(adj_rows, adj_cols, adj_vals, n_edges);
    // 4: emb0 init
    {
        int total4 = N_NODES * D / 4;
        init_kernel<<<(total4 + 255) / 256, 256>>>(user_emb, item_emb);
    }
    // 5-7: fused layers (warp per node, 8 nodes per 256-thread block)
    int layer_blocks = (N_NODES + 7) / 8;
    layer_kernel<<<layer_blocks, 256>>>(0);
    layer_kernel<<<layer_blocks, 256>>>(1);
    layer_kernel<<<layer_blocks, 256>>>(2);
    // 8: final gather + mean
    int gather_rows = 2 * n_ids;
    gather_kernel<<<(gather_rows + 7) / 8, 256>>>(user_id, item_id, out, n_ids);
}

// round 11
// speedup vs baseline: 1.1253x; 1.0653x over previous
#include <cuda_runtime.h>
#include <cuda_fp16.h>
#include <cstdint>

#define N_USERS 50000
#define N_ITEMS 100000
#define N_NODES (N_USERS + N_ITEMS)
#define D 64
#define EPS 1e-6f
#define E_MAX 2400000
#define SCAN_BLOCK 1024
#define N_SCAN_BLOCKS ((N_NODES + SCAN_BLOCK - 1) / SCAN_BLOCK)   // 147

// ---------------------------------------------------------------------------
// Static scratch (allocation-free). Device symbols are ONLY referenced from
// device code (host-side use passes the host shadow address via ATS — R2 bug).
// fp16-ONLY embedding storage: per-layer active set (in 19.2 + out 19.2 +
// CSR 19.2 MB) stays L2-resident AND gather bytes halve. (R6's fp16 *shadow*
// failed because it ADDED to an fp32 master -> 134MB > L2.) All arithmetic
// remains fp32; only storage rounds.
// ---------------------------------------------------------------------------
__device__ __half2 g_embh[4][N_NODES * D / 2];  // fp16 embeddings (layers 0..3)
__device__ int   g_cnt[N_NODES];               // per-row edge counts
__device__ int   g_row_ptr[N_NODES + 1];       // CSR row pointers
__device__ int   g_pos[E_MAX];                 // per-edge within-row rank (from hist)
__device__ int   g_csr_edge[E_MAX * 2];        // interleaved {col, val-bits} pairs
__device__ int   g_is64;                       // index dtype flag
// decoupled-lookback scan state (reset every launch by prep_kernel)
__device__ volatile int g_flag[N_SCAN_BLOCKS];
__device__ volatile int g_aggv[N_SCAN_BLOCKS];
__device__ volatile int g_incv[N_SCAN_BLOCKS];

// ---------------------------------------------------------------------------
// Prep: zero g_cnt + scan flags; block 0 detects index dtype (int64 vs int32)
// in parallel.
// ---------------------------------------------------------------------------
__global__ void prep_kernel(const void* rows, int n) {
    int i = blockIdx.x * blockDim.x + threadIdx.x;
    if (i < N_NODES) g_cnt[i] = 0;
    if (i < N_SCAN_BLOCKS) { g_flag[i] = 0; g_aggv[i] = 0; g_incv[i] = 0; }

    if (blockIdx.x == 0) {
        __shared__ int s_bad;
        if (threadIdx.x == 0) s_bad = 0;
        __syncthreads();
        int lim = (n < 64) ? n : 64;
        if ((int)threadIdx.x < lim) {
            long long v = ((const long long*)rows)[threadIdx.x];
            if (v < 0 || v >= (long long)N_NODES) atomicOr(&s_bad, 1);
        }
        __syncthreads();
        if (threadIdx.x == 0) g_is64 = s_bad ? 0 : 1;
    }
}

__device__ __forceinline__ int load_idx(const void* p, int e) {
    if (g_is64) return (int)((const long long*)p)[e];
    return ((const int*)p)[e];
}

// ---------------------------------------------------------------------------
// Histogram + rank stash: the atomic's return value IS the edge's final
// within-row slot, so the scatter pass needs no atomics at all.
// ---------------------------------------------------------------------------
__global__ void hist_kernel(const void* __restrict__ rows, int n_edges) {
    int e = blockIdx.x * blockDim.x + threadIdx.x;
    if (e >= n_edges) return;
    int r = load_idx(rows, e);
    g_pos[e] = atomicAdd(&g_cnt[r], 1);
}

// ---------------------------------------------------------------------------
// Single-launch decoupled-lookback exclusive scan of g_cnt -> g_row_ptr.
// Warp-parallel lookback (32 predecessors per poll window).
// ---------------------------------------------------------------------------
__global__ void scan_kernel() {
    __shared__ int sh[SCAN_BLOCK];
    __shared__ int s_exc;
    int b = blockIdx.x;
    int i = b * SCAN_BLOCK + threadIdx.x;
    int v = (i < N_NODES) ? g_cnt[i] : 0;
    sh[threadIdx.x] = v;
    __syncthreads();
    #pragma unroll
    for (int off = 1; off < SCAN_BLOCK; off <<= 1) {
        int t = (threadIdx.x >= off) ? sh[threadIdx.x - off] : 0;
        __syncthreads();
        sh[threadIdx.x] += t;
        __syncthreads();
    }
    int total = sh[SCAN_BLOCK - 1];

    if (threadIdx.x < 32) {                 // lookback warp
        int lane = threadIdx.x;
        if (b == 0) {
            if (lane == 0) {
                g_incv[0] = total;
                __threadfence();
                g_flag[0] = 2;
                s_exc = 0;
            }
        } else {
            if (lane == 0) {
                g_aggv[b] = total;
                __threadfence();
                g_flag[b] = 1;
            }
            int run = 0;
            int base = b;                    // window is [base-32, base)
            while (true) {
                int p = base - 32 + lane;
                int f, val;
                if (p >= 0) {
                    while ((f = g_flag[p]) == 0) { }
                    __threadfence();
                    val = (f == 2) ? g_incv[p] : g_aggv[p];
                } else {
                    f = 2; val = 0;          // virtual inclusive prefix of 0
                }
                unsigned mask = __ballot_sync(0xFFFFFFFFu, f == 2);
                if (mask) {
                    int hi = 31 - __clz(mask);
                    int contrib = (lane >= hi) ? val : 0;
                    #pragma unroll
                    for (int o = 16; o; o >>= 1)
                        contrib += __shfl_xor_sync(0xFFFFFFFFu, contrib, o);
                    run += contrib;
                    break;
                } else {
                    int contrib = val;
                    #pragma unroll
                    for (int o = 16; o; o >>= 1)
                        contrib += __shfl_xor_sync(0xFFFFFFFFu, contrib, o);
                    run += contrib;
                    base -= 32;
                }
            }
            if (lane == 0) {
                g_incv[b] = run + total;
                __threadfence();
                g_flag[b] = 2;
                s_exc = run;
            }
        }
    }
    __syncthreads();

    if (i < N_NODES) {
        int inc = sh[threadIdx.x] + s_exc;
        g_row_ptr[i] = inc - v;              // exclusive
        if (i == N_NODES - 1) g_row_ptr[N_NODES] = inc;
    }
}

// ---------------------------------------------------------------------------
// Scatter — atomic-free, ONE packed 8B store per edge (measured win).
// ---------------------------------------------------------------------------
__global__ void scatter_kernel(const void* __restrict__ rows,
                               const void* __restrict__ cols,
                               const float* __restrict__ vals,
                               int n_edges) {
    int e = blockIdx.x * blockDim.x + threadIdx.x;
    if (e >= n_edges) return;
    int r = load_idx(rows, e);
    int c = load_idx(cols, e);
    float v = vals[e];
    int slot = __ldg(&g_row_ptr[r]) + g_pos[e];
    ((int2*)g_csr_edge)[slot] = make_int2(c, __float_as_int(v));
}

// ---------------------------------------------------------------------------
// Init: g_embh[0] = fp16(concat(user_emb, item_emb))
// ---------------------------------------------------------------------------
__global__ void init_kernel(const float* __restrict__ user_emb,
                            const float* __restrict__ item_emb) {
    int i = blockIdx.x * blockDim.x + threadIdx.x;   // float4 index
    const int total4 = N_NODES * D / 4;
    if (i >= total4) return;
    const int usplit = N_USERS * D / 4;
    float4 v = (i < usplit) ? ((const float4*)user_emb)[i]
                            : ((const float4*)item_emb)[i - usplit];
    g_embh[0][i * 2]     = __floats2half2_rn(v.x, v.y);
    g_embh[0][i * 2 + 1] = __floats2half2_rn(v.z, v.w);
}

// ---------------------------------------------------------------------------
// Fused layer (R5/R10-proven loop shape): per-node CSR gather-sum + growth
// gating. One warp per node; lane owns 2 dims (one __half2); 2-way unroll;
// ALL arithmetic fp32, only loads/stores are fp16.
// ---------------------------------------------------------------------------
__global__ void layer_kernel(int l) {
    int node = blockIdx.x * (blockDim.x >> 5) + (threadIdx.x >> 5);
    int lane = threadIdx.x & 31;
    if (node >= N_NODES) return;

    const __half2* baseh = g_embh[l];
    __half2*       outh  = g_embh[l + 1];

    int beg = __ldg(&g_row_ptr[node]);
    int end = __ldg(&g_row_ptr[node + 1]);

    float2 acc = make_float2(0.f, 0.f);

    int i = beg;
    for (; i + 1 < end; i += 2) {
        int   c0 = __ldg(&g_csr_edge[2 * i]);
        float v0 = __int_as_float(__ldg(&g_csr_edge[2 * i + 1]));
        int   c1 = __ldg(&g_csr_edge[2 * i + 2]);
        float v1 = __int_as_float(__ldg(&g_csr_edge[2 * i + 3]));
        float2 x0 = __half22float2(__ldg(&baseh[c0 * 32 + lane]));
        float2 x1 = __half22float2(__ldg(&baseh[c1 * 32 + lane]));
        acc.x += v0 * x0.x + v1 * x1.x;
        acc.y += v0 * x0.y + v1 * x1.y;
    }
    if (i < end) {
        int   c = __ldg(&g_csr_edge[2 * i]);
        float v = __int_as_float(__ldg(&g_csr_edge[2 * i + 1]));
        float2 x = __half22float2(__ldg(&baseh[c * 32 + lane]));
        acc.x += v * x.x;
        acc.y += v * x.y;
    }

    float2 o = __half22float2(baseh[node * 32 + lane]);

    float dx = o.x - acc.x + EPS;
    float dy = o.y - acc.y + EPS;
    float s = dx * dx + dy * dy;
    #pragma unroll
    for (int off = 16; off; off >>= 1)
        s += __shfl_xor_sync(0xFFFFFFFFu, s, off);

    float osn   = sqrtf(s);
    float dnew  = log1pf(osn);
    float inv   = 1.0f / (1.0f + dnew);
    float w_old = inv;
    float w_new = dnew * inv;

    float rx = w_old * o.x + w_new * acc.x;
    float ry = w_old * o.y + w_new * acc.y;
    outh[node * 32 + lane] = __floats2half2_rn(rx, ry);
}

// ---------------------------------------------------------------------------
// Gather: out row = fp32 mean over the 4 fp16 layer embeddings.
// ---------------------------------------------------------------------------
__global__ void gather_kernel(const void* __restrict__ user_id,
                              const void* __restrict__ item_id,
                              float* __restrict__ out,
                              int n_ids) {
    int i = blockIdx.x * (blockDim.x >> 5) + (threadIdx.x >> 5);
    int lane = threadIdx.x & 31;
    if (i >= 2 * n_ids) return;

    int node;
    if (i < n_ids) node = load_idx(user_id, i);
    else           node = N_USERS + load_idx(item_id, i - n_ids);

    int off = node * 32 + lane;
    float2 a0 = __half22float2(g_embh[0][off]);
    float2 a1 = __half22float2(g_embh[1][off]);
    float2 a2 = __half22float2(g_embh[2][off]);
    float2 a3 = __half22float2(g_embh[3][off]);
    float2 r;
    r.x = (a0.x + a1.x + a2.x + a3.x) * 0.25f;
    r.y = (a0.y + a1.y + a2.y + a3.y) * 0.25f;
    ((float2*)(out + (long long)i * D))[lane] = r;
}

// ---------------------------------------------------------------------------
// kernel_launch
// ---------------------------------------------------------------------------
extern "C" void kernel_launch(void* const* d_in, const int* in_sizes, int n_in,
                              void* d_out, int out_size) {
    const float* user_emb = (const float*)d_in[0];
    const float* item_emb = (const float*)d_in[1];
    const float* adj_vals = (const float*)d_in[2];
    const void*  adj_rows = d_in[3];
    const void*  adj_cols = d_in[4];
    const void*  user_id  = d_in[5];
    const void*  item_id  = d_in[6];
    float* out = (float*)d_out;

    int n_edges = in_sizes[3];
    if (n_edges > E_MAX) n_edges = E_MAX;
    int n_ids = in_sizes[5];

    // 0: prep (zero cnt + scan flags + dtype detect)
    prep_kernel<<<(N_NODES + 255) / 256, 256>>>(adj_rows, n_edges);
    // 1: histogram + per-edge rank stash
    hist_kernel<<<(n_edges + 255) / 256, 256>>>(adj_rows, n_edges);
    // 2: single-launch warp-parallel lookback scan -> row_ptr
    scan_kernel<<<N_SCAN_BLOCKS, SCAN_BLOCK>>>();
    // 3: atomic-free scatter, packed 8B store (profiled slot)
    scatter_kernel<<<(n_edges + 255) / 256, 256>>>(adj_rows, adj_cols, adj_vals, n_edges);
    // 4: emb0 init (fp16)
    {
        int total4 = N_NODES * D / 4;
        init_kernel<<<(total4 + 255) / 256, 256>>>(user_emb, item_emb);
    }
    // 5-7: fused layers (warp per node, 8 nodes per 256-thread block)
    int layer_blocks = (N_NODES + 7) / 8;
    layer_kernel<<<layer_blocks, 256>>>(0);
    layer_kernel<<<layer_blocks, 256>>>(1);
    layer_kernel<<<layer_blocks, 256>>>(2);
    // 8: final gather + mean
    int gather_rows = 2 * n_ids;
    gather_kernel<<<(gather_rows + 7) / 8, 256>>>(user_id, item_id, out, n_ids);
}